// round 9
// baseline (speedup 1.0000x reference)
#include <cuda_runtime.h>

// Problem constants (fixed by the dataset: pcd [8, 4096, 3] fp32, k = 5)
#define NB 8
#define NPTS 4096
#define KNN 5
#define GDIM 32
#define GC (GDIM * GDIM * GDIM)

typedef unsigned long long u64;

// Scratch (allocation-free rule -> __device__ globals)
__device__ float4 g_pts[NB * NPTS];    // cell-sorted: x, y, z, |p|^2
__device__ int    g_orig[NB * NPTS];   // original (within-batch) index of sorted slot
__device__ int    g_cellid[NB * NPTS]; // per-point cell id (original order)
__device__ int    g_cnt[NB * GC];
__device__ int    g_startA[NB * GC];
__device__ int    g_cursor[NB * GC];
__device__ float  g_bbox[NB][8];       // minx,miny,minz, invwx,invwy,invwz, wmin
__device__ float  g_partial[NB * 16];  // per-psum-CTA trace partial sums

// --------------------------------------------------------------------------
// K1: per-batch bounding box -> cell geometry.
// --------------------------------------------------------------------------
__global__ __launch_bounds__(256) void bbox_kernel(const float* __restrict__ pcd)
{
    __shared__ float sm[6][8];
    const int b = blockIdx.x;
    const float* base = pcd + (size_t)b * NPTS * 3;

    float mnx = 1e30f, mny = 1e30f, mnz = 1e30f;
    float mxx = -1e30f, mxy = -1e30f, mxz = -1e30f;
    for (int i = threadIdx.x; i < NPTS; i += 256) {
        float x = base[i * 3 + 0], y = base[i * 3 + 1], z = base[i * 3 + 2];
        mnx = fminf(mnx, x); mny = fminf(mny, y); mnz = fminf(mnz, z);
        mxx = fmaxf(mxx, x); mxy = fmaxf(mxy, y); mxz = fmaxf(mxz, z);
    }
#pragma unroll
    for (int off = 16; off; off >>= 1) {
        mnx = fminf(mnx, __shfl_xor_sync(0xffffffffu, mnx, off));
        mny = fminf(mny, __shfl_xor_sync(0xffffffffu, mny, off));
        mnz = fminf(mnz, __shfl_xor_sync(0xffffffffu, mnz, off));
        mxx = fmaxf(mxx, __shfl_xor_sync(0xffffffffu, mxx, off));
        mxy = fmaxf(mxy, __shfl_xor_sync(0xffffffffu, mxy, off));
        mxz = fmaxf(mxz, __shfl_xor_sync(0xffffffffu, mxz, off));
    }
    const int wid = threadIdx.x >> 5, lane = threadIdx.x & 31;
    if (lane == 0) {
        sm[0][wid] = mnx; sm[1][wid] = mny; sm[2][wid] = mnz;
        sm[3][wid] = mxx; sm[4][wid] = mxy; sm[5][wid] = mxz;
    }
    __syncthreads();
    if (threadIdx.x == 0) {
        float a0 = sm[0][0], a1 = sm[1][0], a2 = sm[2][0];
        float a3 = sm[3][0], a4 = sm[4][0], a5 = sm[5][0];
        for (int w = 1; w < 8; w++) {
            a0 = fminf(a0, sm[0][w]); a1 = fminf(a1, sm[1][w]); a2 = fminf(a2, sm[2][w]);
            a3 = fmaxf(a3, sm[3][w]); a4 = fmaxf(a4, sm[4][w]); a5 = fmaxf(a5, sm[5][w]);
        }
        float ex = (a3 - a0) + 1e-5f;
        float ey = (a4 - a1) + 1e-5f;
        float ez = (a5 - a2) + 1e-5f;
        g_bbox[b][0] = a0; g_bbox[b][1] = a1; g_bbox[b][2] = a2;
        g_bbox[b][3] = (float)GDIM / ex;
        g_bbox[b][4] = (float)GDIM / ey;
        g_bbox[b][5] = (float)GDIM / ez;
        g_bbox[b][6] = fminf(ex, fminf(ey, ez)) / (float)GDIM;   // wmin
    }
}

// --------------------------------------------------------------------------
// K2: zero cell counts.
// --------------------------------------------------------------------------
__global__ __launch_bounds__(1024) void zero_kernel()
{
    g_cnt[blockIdx.x * 1024 + threadIdx.x] = 0;
}

// --------------------------------------------------------------------------
// K3: assign cell ids + histogram.
// --------------------------------------------------------------------------
__global__ __launch_bounds__(256) void cell_count_kernel(const float* __restrict__ pcd)
{
    const int t = blockIdx.x * 256 + threadIdx.x;   // 0 .. NB*NPTS-1
    const int b = t >> 12;
    const float* p = pcd + (size_t)t * 3;
    const float x = p[0], y = p[1], z = p[2];
    int cx = (int)((x - g_bbox[b][0]) * g_bbox[b][3]);
    int cy = (int)((y - g_bbox[b][1]) * g_bbox[b][4]);
    int cz = (int)((z - g_bbox[b][2]) * g_bbox[b][5]);
    cx = min(GDIM - 1, max(0, cx));
    cy = min(GDIM - 1, max(0, cy));
    cz = min(GDIM - 1, max(0, cz));
    const int cid = (cz * GDIM + cy) * GDIM + cx;
    g_cellid[t] = cid;
    atomicAdd(&g_cnt[b * GC + cid], 1);
}

// --------------------------------------------------------------------------
// K4: per-batch exclusive scan of the 32768 cell counts (one CTA per batch).
// Writes bucket starts and initializes scatter cursors.
// --------------------------------------------------------------------------
__global__ __launch_bounds__(1024) void scan_kernel()
{
    __shared__ int wsum[32];
    const int b = blockIdx.x;
    const int base = b * GC;
    const int tid = threadIdx.x;
    const int lane = tid & 31, wid = tid >> 5;
    const int c0 = tid * (GC / 1024);               // 32 cells per thread

    int T = 0;
    for (int i = 0; i < GC / 1024; i++) T += g_cnt[base + c0 + i];

    int incl = T;
#pragma unroll
    for (int off = 1; off < 32; off <<= 1) {
        int n = __shfl_up_sync(0xffffffffu, incl, off);
        if (lane >= off) incl += n;
    }
    if (lane == 31) wsum[wid] = incl;
    __syncthreads();
    if (wid == 0) {
        int v = wsum[lane];
        int iv = v;
#pragma unroll
        for (int off = 1; off < 32; off <<= 1) {
            int n = __shfl_up_sync(0xffffffffu, iv, off);
            if (lane >= off) iv += n;
        }
        wsum[lane] = iv - v;                        // exclusive warp prefix
    }
    __syncthreads();

    int run = wsum[wid] + (incl - T);               // exclusive thread offset
    for (int i = 0; i < GC / 1024; i++) {
        const int c = g_cnt[base + c0 + i];
        g_startA[base + c0 + i] = run;
        g_cursor[base + c0 + i] = run;
        run += c;
    }
}

// --------------------------------------------------------------------------
// K5: scatter points into cell buckets (order within bucket nondeterministic,
// output stays deterministic: selection uses a strict total order on
// (key, original index), and sums run in rank order).
// --------------------------------------------------------------------------
__global__ __launch_bounds__(256) void scatter_kernel(const float* __restrict__ pcd)
{
    const int t = blockIdx.x * 256 + threadIdx.x;
    const int b = t >> 12;
    const int i = t & (NPTS - 1);
    const int cid = g_cellid[t];
    const int pos = atomicAdd(&g_cursor[b * GC + cid], 1);
    const float* p = pcd + (size_t)t * 3;
    const float x = p[0], y = p[1], z = p[2];
    g_pts[b * NPTS + pos] = make_float4(x, y, z, fmaf(x, x, fmaf(y, y, z * z)));
    g_orig[b * NPTS + pos] = i;
}

// --------------------------------------------------------------------------
// K6: expanding-shell exact kNN + covariance trace.
// key = max(|p|^2 + |q|^2 - 2 q.p, 0) == reference's max(d2, 0); packed as
// (key_bits << 32) | orig_idx so u64 '<' is exactly top_k's order
// (smaller distance first, lowest index on ties).
// --------------------------------------------------------------------------
__device__ __forceinline__ void proc_cell(
    int cbase, int sbase, int cid,
    float nx, float ny, float nz, float q2,
    u64& h0, u64& h1, u64& h2, u64& h3, u64& h4)
{
    const int cs = g_startA[cbase + cid];
    const int cc = g_cnt[cbase + cid];
    const float4* P = g_pts + sbase + cs;
    const int* O = g_orig + sbase + cs;
    for (int i = 0; i < cc; i++) {
        float4 p = P[i];
        float key = fmaf(p.x, nx, fmaf(p.y, ny, fmaf(p.z, nz, p.w + q2)));
        key = fmaxf(key, 0.0f);
        u64 cand = ((u64)__float_as_uint(key) << 32) | (unsigned)O[i];
        if (cand < h4) {
            bool l0 = cand < h0, l1 = cand < h1, l2 = cand < h2, l3 = cand < h3;
            h4 = l3 ? h3 : cand;
            if (l3) { h3 = l2 ? h2 : cand;
            if (l2) { h2 = l1 ? h1 : cand;
            if (l1) { h1 = l0 ? h0 : cand;
            if (l0) { h0 = cand; } } } }
        }
    }
}

__global__ __launch_bounds__(128) void query_kernel(
    const float* __restrict__ pcd, float* __restrict__ out)
{
    const int t = blockIdx.x * 128 + threadIdx.x;   // sorted slot
    const int b = t >> 12;
    const int cbase = b * GC;
    const int sbase = b * NPTS;

    const float minx = g_bbox[b][0], miny = g_bbox[b][1], minz = g_bbox[b][2];
    const float iwx = g_bbox[b][3], iwy = g_bbox[b][4], iwz = g_bbox[b][5];
    const float wmin = g_bbox[b][6];

    const float4 q = g_pts[t];
    const int oi = g_orig[t];
    const float nx = -2.0f * q.x, ny = -2.0f * q.y, nz = -2.0f * q.z;
    const float q2 = q.w;

    int cx = min(GDIM - 1, max(0, (int)((q.x - minx) * iwx)));
    int cy = min(GDIM - 1, max(0, (int)((q.y - miny) * iwy)));
    int cz = min(GDIM - 1, max(0, (int)((q.z - minz) * iwz)));

    u64 h0 = ~0ull, h1 = ~0ull, h2 = ~0ull, h3 = ~0ull, h4 = ~0ull;

#define PROCC(X, Y, Z) proc_cell(cbase, sbase, ((Z) * GDIM + (Y)) * GDIM + (X), \
                                 nx, ny, nz, q2, h0, h1, h2, h3, h4)

    for (int s = 0; s < GDIM; s++) {
        if (s == 0) {
            PROCC(cx, cy, cz);
        } else {
            const int x0 = max(cx - s, 0), x1 = min(cx + s, GDIM - 1);
            const int y0 = max(cy - s, 0), y1 = min(cy + s, GDIM - 1);
            const int zi0 = max(cz - s + 1, 0), zi1 = min(cz + s - 1, GDIM - 1);
            const int yi0 = max(cy - s + 1, 0), yi1 = min(cy + s - 1, GDIM - 1);
            // z faces: |dz| = s, dy/dx full
            if (cz - s >= 0)
                for (int y = y0; y <= y1; y++)
                    for (int x = x0; x <= x1; x++) PROCC(x, y, cz - s);
            if (cz + s < GDIM)
                for (int y = y0; y <= y1; y++)
                    for (int x = x0; x <= x1; x++) PROCC(x, y, cz + s);
            // y faces: |dy| = s, dz inner, dx full
            if (cy - s >= 0)
                for (int z = zi0; z <= zi1; z++)
                    for (int x = x0; x <= x1; x++) PROCC(x, cy - s, z);
            if (cy + s < GDIM)
                for (int z = zi0; z <= zi1; z++)
                    for (int x = x0; x <= x1; x++) PROCC(x, cy + s, z);
            // x faces: |dx| = s, dz inner, dy inner
            if (cx - s >= 0)
                for (int z = zi0; z <= zi1; z++)
                    for (int y = yi0; y <= yi1; y++) PROCC(cx - s, y, z);
            if (cx + s < GDIM)
                for (int z = zi0; z <= zi1; z++)
                    for (int y = yi0; y <= yi1; y++) PROCC(cx + s, y, z);
        }
        // Stop: unscanned cells have distance >= s*wmin. Margin covers fp
        // error in keys and in the bound. If <5 found, k5 bits are 0xFFFFFFFF
        // (NaN) and the comparison is false -> keep expanding.
        const float k5 = __uint_as_float((unsigned)(h4 >> 32));
        const float lim = (float)s * wmin;
        if (k5 <= lim * lim * 0.999f - 1e-4f) break;
    }
#undef PROCC

    // Gather the 5 neighbors by original index; reference numerics.
    const float* basep = pcd + (size_t)b * NPTS * 3;
    float px[KNN], py[KNN], pz[KNN];
    const unsigned id0 = (unsigned)h0, id1 = (unsigned)h1, id2 = (unsigned)h2,
                   id3 = (unsigned)h3, id4 = (unsigned)h4;
    px[0] = basep[id0 * 3 + 0]; py[0] = basep[id0 * 3 + 1]; pz[0] = basep[id0 * 3 + 2];
    px[1] = basep[id1 * 3 + 0]; py[1] = basep[id1 * 3 + 1]; pz[1] = basep[id1 * 3 + 2];
    px[2] = basep[id2 * 3 + 0]; py[2] = basep[id2 * 3 + 1]; pz[2] = basep[id2 * 3 + 2];
    px[3] = basep[id3 * 3 + 0]; py[3] = basep[id3 * 3 + 1]; pz[3] = basep[id3 * 3 + 2];
    px[4] = basep[id4 * 3 + 0]; py[4] = basep[id4 * 3 + 1]; pz[4] = basep[id4 * 3 + 2];

    const float inv_k = 1.0f / (float)KNN;
    float mx = (px[0] + px[1] + px[2] + px[3] + px[4]) * inv_k;
    float my = (py[0] + py[1] + py[2] + py[3] + py[4]) * inv_k;
    float mz = (pz[0] + pz[1] + pz[2] + pz[3] + pz[4]) * inv_k;

    float tr = 0.0f;
#pragma unroll
    for (int c = 0; c < KNN; c++) {
        float dx = px[c] - mx, dy = py[c] - my, dz = pz[c] - mz;
        tr = fmaf(dx, dx, fmaf(dy, dy, fmaf(dz, dz, tr)));
    }
    tr *= 1.0f / (float)(KNN - 1);
    out[b * NPTS + oi] = tr;
}

// --------------------------------------------------------------------------
// K7: deterministic per-CTA partial sums of traces (original index order).
// --------------------------------------------------------------------------
__global__ __launch_bounds__(256) void psum_kernel(const float* __restrict__ out)
{
    __shared__ float warp_sums[8];
    const int t = blockIdx.x * 256 + threadIdx.x;
    float s = out[t];
#pragma unroll
    for (int off = 16; off > 0; off >>= 1)
        s += __shfl_down_sync(0xffffffffu, s, off);
    if ((threadIdx.x & 31) == 0) warp_sums[threadIdx.x >> 5] = s;
    __syncthreads();
    if (threadIdx.x < 32) {
        float v = (threadIdx.x < 8) ? warp_sums[threadIdx.x] : 0.0f;
#pragma unroll
        for (int off = 4; off > 0; off >>= 1)
            v += __shfl_down_sync(0xffffffffu, v, off);
        if (threadIdx.x == 0) g_partial[blockIdx.x] = v;
    }
}

// --------------------------------------------------------------------------
// K8: normalize. 4 CTAs per batch; each redundantly sums its batch's 16
// partials with a fixed-order tree (deterministic) and scales its quarter.
// --------------------------------------------------------------------------
__global__ __launch_bounds__(256) void finalize_kernel(float* __restrict__ out)
{
    __shared__ float s_inv;
    const int b = blockIdx.x >> 2;
    const int quarter = blockIdx.x & 3;

    if (threadIdx.x < 32) {
        float v = (threadIdx.x < 16) ? g_partial[b * 16 + threadIdx.x] : 0.0f;
#pragma unroll
        for (int off = 8; off > 0; off >>= 1)
            v += __shfl_down_sync(0xffffffffu, v, off);
        if (threadIdx.x == 0) s_inv = 1.0f / (v + 1e-8f);
    }
    __syncthreads();

    const float inv = s_inv;
    float* o = out + (size_t)b * NPTS + quarter * (NPTS / 4);
#pragma unroll
    for (int i = 0; i < (NPTS / 4) / 256; i++)
        o[i * 256 + threadIdx.x] *= inv;
}

extern "C" void kernel_launch(void* const* d_in, const int* in_sizes, int n_in,
                              void* d_out, int out_size)
{
    const float* pcd = (const float*)d_in[0];
    float* out = (float*)d_out;

    bbox_kernel<<<NB, 256>>>(pcd);
    zero_kernel<<<(NB * GC) / 1024, 1024>>>();
    cell_count_kernel<<<(NB * NPTS) / 256, 256>>>(pcd);
    scan_kernel<<<NB, 1024>>>();
    scatter_kernel<<<(NB * NPTS) / 256, 256>>>(pcd);
    query_kernel<<<(NB * NPTS) / 128, 128>>>(pcd, out);
    psum_kernel<<<(NB * NPTS) / 256, 256>>>(out);
    finalize_kernel<<<NB * 4, 256>>>(out);
}

// round 10
// speedup vs baseline: 5.9775x; 5.9775x over previous
#include <cuda_runtime.h>

// Problem constants (fixed by the dataset: pcd [8, 4096, 3] fp32, k = 5)
#define NB 8
#define NPTS 4096
#define KNN 5
#define NSPLIT 4
#define MSEG (NPTS / NSPLIT)       // 1024 points per segment
#define MPAIR (MSEG / 2)           // 512 point-pairs
#define TPB 128
#define CHUNKS (NPTS / TPB)        // 32 query chunks per batch

typedef unsigned long long u64;

// Scratch (allocation-free rule -> __device__ globals)
__device__ float g_key[NSPLIT][NB * NPTS * KNN];
__device__ int   g_idx[NSPLIT][NB * NPTS * KNN];
__device__ float g_partial[NB * 16];   // per-merge-CTA trace partial sums

// Packed f32x2 helpers (Blackwell FFMA2 is PTX-only).
__device__ __forceinline__ u64 pack2(float lo, float hi) {
    u64 r;
    asm("mov.b64 %0, {%1, %2};" : "=l"(r)
        : "r"(__float_as_uint(lo)), "r"(__float_as_uint(hi)));
    return r;
}
__device__ __forceinline__ u64 ffma2(u64 a, u64 b, u64 c) {
    u64 d;
    asm("fma.rn.f32x2 %0, %1, %2, %3;" : "=l"(d) : "l"(a), "l"(b), "l"(c));
    return d;
}
__device__ __forceinline__ void unpack2(u64 v, float& lo, float& hi) {
    unsigned l, h;
    asm("mov.b64 {%0, %1}, %2;" : "=r"(l), "=r"(h) : "l"(v));
    lo = __uint_as_float(l);
    hi = __uint_as_float(h);
}

// --------------------------------------------------------------------------
// Kernel A: per-(query, point-segment) top-5 scan, pair-packed.
// CTA = 128 queries x one quarter of the points. The 1024-pt segment is
// staged as 512 pairs: shA[m] = (x0x1, y0y1), shB[m] = (z0z1, |p0|^2|p1|^2),
// 16KB total. Per pair: 2 x LDS.128 + 3 x FFMA2 -> two keys, then two
// individually-guarded exact register inserts.
// key_j = |p_j|^2 - 2 q.p_j (monotone in d^2 for fixed q; strict '<'
// displacement keeps the lowest index on ties, matching jax.lax.top_k).
// --------------------------------------------------------------------------
__global__ __launch_bounds__(TPB) void knn_scan_kernel(const float* __restrict__ pcd)
{
    __shared__ ulonglong2 shA[MPAIR];   // 8 KB: x-pair, y-pair
    __shared__ ulonglong2 shB[MPAIR];   // 8 KB: z-pair, w-pair

    const int seg   = blockIdx.x & (NSPLIT - 1);
    const int chunk = (blockIdx.x >> 2) % CHUNKS;
    const int b     = blockIdx.x / (NSPLIT * CHUNKS);

    const float* base = pcd + (size_t)b * NPTS * 3;
    const int p0 = seg * MSEG;

    for (int m = threadIdx.x; m < MPAIR; m += TPB) {
        const float* pp = base + (size_t)(p0 + 2 * m) * 3;
        float x0 = pp[0], y0 = pp[1], z0 = pp[2];
        float x1 = pp[3], y1 = pp[4], z1 = pp[5];
        float w0 = fmaf(x0, x0, fmaf(y0, y0, z0 * z0));
        float w1 = fmaf(x1, x1, fmaf(y1, y1, z1 * z1));
        ulonglong2 va, vb;
        va.x = pack2(x0, x1);  va.y = pack2(y0, y1);
        vb.x = pack2(z0, z1);  vb.y = pack2(w0, w1);
        shA[m] = va;
        shB[m] = vb;
    }
    __syncthreads();

    const int qi = chunk * TPB + threadIdx.x;
    const float qx = base[qi * 3 + 0];
    const float qy = base[qi * 3 + 1];
    const float qz = base[qi * 3 + 2];
    const u64 nx2 = pack2(-2.0f * qx, -2.0f * qx);
    const u64 ny2 = pack2(-2.0f * qy, -2.0f * qy);
    const u64 nz2 = pack2(-2.0f * qz, -2.0f * qz);

    // Exact sorted top-5 (ascending); named scalars -> registers.
    float bk0 = 3.4e38f, bk1 = 3.4e38f, bk2 = 3.4e38f, bk3 = 3.4e38f, bk4 = 3.4e38f;
    int   bi0 = 0, bi1 = 0, bi2 = 0, bi3 = 0, bi4 = 0;

#define INSERT(KEY, JIDX)                                                     \
    {                                                                         \
        float key = (KEY);                                                    \
        if (key < bk4) {                                                      \
            bool lt0 = key < bk0;                                             \
            bool lt1 = key < bk1;                                             \
            bool lt2 = key < bk2;                                             \
            bool lt3 = key < bk3;                                             \
            bk4 = lt3 ? bk3 : key;  bi4 = lt3 ? bi3 : (JIDX);                 \
            if (lt3) { bk3 = lt2 ? bk2 : key;  bi3 = lt2 ? bi2 : (JIDX); }    \
            if (lt2) { bk2 = lt1 ? bk1 : key;  bi2 = lt1 ? bi1 : (JIDX); }    \
            if (lt1) { bk1 = lt0 ? bk0 : key;  bi1 = lt0 ? bi0 : (JIDX); }    \
            if (lt0) { bk0 = key;              bi0 = (JIDX); }                \
        }                                                                     \
    }

    for (int m = 0; m < MPAIR; m += 4) {
        // Batched loads: 8 x LDS.128 back-to-back (one basic block).
        ulonglong2 a0 = shA[m + 0], b0 = shB[m + 0];
        ulonglong2 a1 = shA[m + 1], b1 = shB[m + 1];
        ulonglong2 a2 = shA[m + 2], b2 = shB[m + 2];
        ulonglong2 a3 = shA[m + 3], b3 = shB[m + 3];
        // All keys straight-line: 3 FFMA2 per pair.
        u64 kk0 = ffma2(a0.x, nx2, ffma2(a0.y, ny2, ffma2(b0.x, nz2, b0.y)));
        u64 kk1 = ffma2(a1.x, nx2, ffma2(a1.y, ny2, ffma2(b1.x, nz2, b1.y)));
        u64 kk2 = ffma2(a2.x, nx2, ffma2(a2.y, ny2, ffma2(b2.x, nz2, b2.y)));
        u64 kk3 = ffma2(a3.x, nx2, ffma2(a3.y, ny2, ffma2(b3.x, nz2, b3.y)));
        float k0a, k0b, k1a, k1b, k2a, k2b, k3a, k3b;
        unpack2(kk0, k0a, k0b);
        unpack2(kk1, k1a, k1b);
        unpack2(kk2, k2a, k2b);
        unpack2(kk3, k3a, k3b);
        const int jb = p0 + 2 * m;
        INSERT(k0a, jb + 0);
        INSERT(k0b, jb + 1);
        INSERT(k1a, jb + 2);
        INSERT(k1b, jb + 3);
        INSERT(k2a, jb + 4);
        INSERT(k2b, jb + 5);
        INSERT(k3a, jb + 6);
        INSERT(k3b, jb + 7);
    }
#undef INSERT

    const size_t o = ((size_t)b * NPTS + qi) * KNN;
    g_key[seg][o + 0] = bk0;  g_idx[seg][o + 0] = bi0;
    g_key[seg][o + 1] = bk1;  g_idx[seg][o + 1] = bi1;
    g_key[seg][o + 2] = bk2;  g_idx[seg][o + 2] = bi2;
    g_key[seg][o + 3] = bk3;  g_idx[seg][o + 3] = bi3;
    g_key[seg][o + 4] = bk4;  g_idx[seg][o + 4] = bi4;
}

// --------------------------------------------------------------------------
// Kernel B: merge the four sorted 5-lists per query by rank counting.
// Global order = (key, segment, in-list position): earlier segment wins ties
// ('<=' vs '<'). Gather neighbors, compute covariance trace with the
// reference's centroid-then-centered numerics. Emits per-CTA partial sums.
// --------------------------------------------------------------------------
__global__ __launch_bounds__(256) void merge_trace_kernel(
    const float* __restrict__ pcd, float* __restrict__ out)
{
    __shared__ float warp_sums[8];

    const int t = blockIdx.x * 256 + threadIdx.x;   // 0 .. NB*NPTS-1
    const int b = t >> 12;

    float k[NSPLIT][KNN];
    int   ix[NSPLIT][KNN];
    const size_t o = (size_t)t * KNN;
#pragma unroll
    for (int s = 0; s < NSPLIT; s++)
#pragma unroll
        for (int i = 0; i < KNN; i++) {
            k[s][i]  = g_key[s][o + i];
            ix[s][i] = g_idx[s][o + i];
        }

    float w[NSPLIT][KNN];
#pragma unroll
    for (int s = 0; s < NSPLIT; s++) {
#pragma unroll
        for (int i = 0; i < KNN; i++) {
            int r = i;
#pragma unroll
            for (int u = 0; u < NSPLIT; u++) {
                if (u == s) continue;
#pragma unroll
                for (int j = 0; j < KNN; j++) {
                    if (u < s) r += (k[u][j] <= k[s][i]);
                    else       r += (k[u][j] <  k[s][i]);
                }
            }
            w[s][i] = (r < KNN) ? 1.0f : 0.0f;
        }
    }

    const float* base = pcd + (size_t)b * NPTS * 3;
    float px[NSPLIT][KNN], py[NSPLIT][KNN], pz[NSPLIT][KNN];
#pragma unroll
    for (int s = 0; s < NSPLIT; s++)
#pragma unroll
        for (int i = 0; i < KNN; i++) {
            int idx = ix[s][i];
            px[s][i] = base[idx * 3 + 0];
            py[s][i] = base[idx * 3 + 1];
            pz[s][i] = base[idx * 3 + 2];
        }

    float sx = 0.f, sy = 0.f, sz = 0.f;
#pragma unroll
    for (int s = 0; s < NSPLIT; s++)
#pragma unroll
        for (int i = 0; i < KNN; i++) {
            sx = fmaf(w[s][i], px[s][i], sx);
            sy = fmaf(w[s][i], py[s][i], sy);
            sz = fmaf(w[s][i], pz[s][i], sz);
        }
    const float inv_k = 1.0f / (float)KNN;
    const float mx = sx * inv_k, my = sy * inv_k, mz = sz * inv_k;

    float tr = 0.f;
#pragma unroll
    for (int s = 0; s < NSPLIT; s++)
#pragma unroll
        for (int i = 0; i < KNN; i++) {
            float dx = px[s][i] - mx, dy = py[s][i] - my, dz = pz[s][i] - mz;
            tr = fmaf(w[s][i], fmaf(dx, dx, fmaf(dy, dy, dz * dz)), tr);
        }
    tr *= 1.0f / (float)(KNN - 1);
    out[t] = tr;

    float s0 = tr;
#pragma unroll
    for (int off = 16; off > 0; off >>= 1)
        s0 += __shfl_down_sync(0xffffffffu, s0, off);
    if ((threadIdx.x & 31) == 0) warp_sums[threadIdx.x >> 5] = s0;
    __syncthreads();
    if (threadIdx.x < 32) {
        float v = (threadIdx.x < 8) ? warp_sums[threadIdx.x] : 0.0f;
#pragma unroll
        for (int off = 4; off > 0; off >>= 1)
            v += __shfl_down_sync(0xffffffffu, v, off);
        if (threadIdx.x == 0) g_partial[blockIdx.x] = v;
    }
}

// --------------------------------------------------------------------------
// Kernel C: normalize. 4 CTAs per batch; each redundantly sums its batch's
// 16 partials with a fixed-order tree (deterministic) and scales its quarter.
// --------------------------------------------------------------------------
__global__ __launch_bounds__(256) void finalize_kernel(float* __restrict__ out)
{
    __shared__ float s_inv;
    const int b = blockIdx.x >> 2;
    const int quarter = blockIdx.x & 3;

    if (threadIdx.x < 32) {
        float v = (threadIdx.x < 16) ? g_partial[b * 16 + threadIdx.x] : 0.0f;
#pragma unroll
        for (int off = 8; off > 0; off >>= 1)
            v += __shfl_down_sync(0xffffffffu, v, off);
        if (threadIdx.x == 0) s_inv = 1.0f / (v + 1e-8f);
    }
    __syncthreads();

    const float inv = s_inv;
    float* o = out + (size_t)b * NPTS + quarter * (NPTS / 4);
#pragma unroll
    for (int i = 0; i < (NPTS / 4) / 256; i++)
        o[i * 256 + threadIdx.x] *= inv;
}

extern "C" void kernel_launch(void* const* d_in, const int* in_sizes, int n_in,
                              void* d_out, int out_size)
{
    const float* pcd = (const float*)d_in[0];
    float* out = (float*)d_out;

    knn_scan_kernel<<<NB * CHUNKS * NSPLIT, TPB>>>(pcd);      // 1024 CTAs
    merge_trace_kernel<<<(NB * NPTS) / 256, 256>>>(pcd, out); // 128 CTAs
    finalize_kernel<<<NB * 4, 256>>>(out);                    // 32 CTAs
}